// round 13
// baseline (speedup 1.0000x reference)
#include <cuda_runtime.h>
#include <cstdint>

// Depthwise conv1d, K=7, 'same' padding, softmax over taps.
// x: (B, C, T) fp32; weight: (H, 1, 7); head for channel c is c % H (H=16).
//
// PERSISTENT single kernel: 1024 CTAs grid-stride over 32768 tiles (exactly
// 32 each). Softmax for ALL 16 heads computed ONCE per CTA in the prologue
// (amortized ~0), then R2's proven tile body (TILE=2048, 8KB smem, MLP=2,
// register-reused middle chunk; best measured: 80.7% DRAM).

#define KSIZE 7
#define TILE 2048
#define HALF (TILE / 2)
#define THREADS 256
#define SHIFT 4    // s[SHIFT + i] = x[t0 + i]; halo lives at s[1..3]
#define T_LEN 4096
#define NTILES 32768   // rows(16384) * 2 tiles per row
#define GRID 1024      // divides NTILES exactly (32 tiles per CTA)

__global__ __launch_bounds__(THREADS, 7)
void lconv1d_persist_kernel(const float* __restrict__ x,
                            const float* __restrict__ wraw,
                            float* __restrict__ out) {
    __shared__ float s[SHIFT + TILE + 3];
    __shared__ __align__(16) float sw[16][8];   // all heads, padded to 8

    const int tid = threadIdx.x;
    const int p0 = tid * 4;
    const int p1 = p0 + HALF;

    // Prologue: softmax for all 16 heads, once per CTA (threads 0..15).
    if (tid < 16) {
        float v[KSIZE];
        float m = -1e30f;
        #pragma unroll
        for (int k = 0; k < KSIZE; k++) {
            v[k] = __ldg(&wraw[tid * KSIZE + k]);
            m = fmaxf(m, v[k]);
        }
        float sum = 0.f;
        #pragma unroll
        for (int k = 0; k < KSIZE; k++) sum += __expf(v[k] - m);
        const float inv = 1.f / sum;
        #pragma unroll
        for (int k = 0; k < KSIZE; k++) sw[tid][k] = __expf(v[k] - m) * inv;
        sw[tid][7] = 0.f;
    }
    // (sw visibility covered by the first in-loop __syncthreads after STS.)

    for (int tile = blockIdx.x; tile < NTILES; tile += GRID) {
        const int row = tile >> 1;
        const int t0  = (tile & 1) * TILE;
        const size_t base = (size_t)row * T_LEN + t0;

        // Two independent main-tile loads (MLP=2), aligned STS.128.
        const float4 v0 = *reinterpret_cast<const float4*>(x + base + p0);
        const float4 v1 = *reinterpret_cast<const float4*>(x + base + p1);
        *reinterpret_cast<float4*>(&s[SHIFT + p0]) = v0;
        *reinterpret_cast<float4*>(&s[SHIFT + p1]) = v1;

        // Halos (3 left, 3 right), zero-padded at row boundaries.
        if (tid < 3) {
            s[1 + tid]            = (t0 > 0)            ? x[base - 3 + tid]    : 0.f;
            s[SHIFT + TILE + tid] = (t0 + TILE < T_LEN) ? x[base + TILE + tid] : 0.f;
        }

        __syncthreads();

        // Weights for this row's head: two broadcast LDS.128.
        const int h = row & 15;                 // C=1024 multiple of H=16
        const float4 wa = *reinterpret_cast<const float4*>(&sw[h][0]);
        const float4 wb = *reinterpret_cast<const float4*>(&sw[h][4]);
        const float w0 = wa.x, w1 = wa.y, w2 = wa.z, w3 = wa.w,
                    w4 = wb.x, w5 = wb.y, w6 = wb.z;

        // Chunk 0: outputs [p0 .. p0+3]. Middle float4 == v0 (register reuse).
        {
            const float4 a = *reinterpret_cast<const float4*>(&s[p0]);
            const float4 b = v0;
            const float4 c = *reinterpret_cast<const float4*>(&s[p0 + 8]);
            float4 r;
            r.x = w0*a.y + w1*a.z + w2*a.w + w3*b.x + w4*b.y + w5*b.z + w6*b.w;
            r.y = w0*a.z + w1*a.w + w2*b.x + w3*b.y + w4*b.z + w5*b.w + w6*c.x;
            r.z = w0*a.w + w1*b.x + w2*b.y + w3*b.z + w4*b.w + w5*c.x + w6*c.y;
            r.w = w0*b.x + w1*b.y + w2*b.z + w3*b.w + w4*c.x + w5*c.y + w6*c.z;
            *reinterpret_cast<float4*>(out + base + p0) = r;
        }

        // Chunk 1: outputs [p1 .. p1+3]. Middle float4 == v1.
        {
            const float4 a = *reinterpret_cast<const float4*>(&s[p1]);
            const float4 b = v1;
            const float4 c = *reinterpret_cast<const float4*>(&s[p1 + 8]);
            float4 r;
            r.x = w0*a.y + w1*a.z + w2*a.w + w3*b.x + w4*b.y + w5*b.z + w6*b.w;
            r.y = w0*a.z + w1*a.w + w2*b.x + w3*b.y + w4*b.z + w5*b.w + w6*c.x;
            r.z = w0*a.w + w1*b.x + w2*b.y + w3*b.z + w4*b.w + w5*c.x + w6*c.y;
            r.w = w0*b.x + w1*b.y + w2*b.z + w3*b.w + w4*c.x + w5*c.y + w6*c.z;
            *reinterpret_cast<float4*>(out + base + p1) = r;
        }

        __syncthreads();   // protect s before next iteration's STS
    }
}

extern "C" void kernel_launch(void* const* d_in, const int* in_sizes, int n_in,
                              void* d_out, int out_size) {
    const float* x = (const float*)d_in[0];
    const float* w = (const float*)d_in[1];
    float* out = (float*)d_out;

    lconv1d_persist_kernel<<<GRID, THREADS>>>(x, w, out);
}